// round 8
// baseline (speedup 1.0000x reference)
#include <cuda_runtime.h>

// Potts energy: out[b] = sum_{i<=j} W[i,j] * [(1-x_i)(1-x_j) + x_i*x_j]
// Expand: (1-x_i)(1-x_j)+x_i x_j = 1 - x_i - x_j + 2 x_i x_j
// Per 64x64 tile U = masked W, split into TWO 32-row i-halves (one CTA each):
//   E_half(b) = Wsum_h - sum_{i in half} rs_i x_bi - sum_j cs_h_j x_bj
//             + 2 sum_{i in half, j} U_ij x_bi x_bj
// Quadratic part packed over batch pairs with W duplicated as (w,w) u64.
// grid = 272 (136 tiles x 2 halves) -> ~2 CTAs/SM, 32 warps/SM.

#define Bb      128
#define Nn      1024
#define T       64
#define HI      32      // i-rows per CTA (half tile)
#define NT      16
#define NCTAS   272
#define WDS     66      // Wdup row stride (u64)
#define XS      66      // Xi/Xj row stride (u64)
#define THREADS 512

__device__ float        g_accum[Bb];
__device__ unsigned int g_count;

__device__ __forceinline__ unsigned long long pack2(float lo, float hi) {
    unsigned long long r;
    asm("mov.b64 %0, {%1, %2};" : "=l"(r) : "f"(lo), "f"(hi));
    return r;
}
__device__ __forceinline__ void unpack2(unsigned long long v, float& lo, float& hi) {
    asm("mov.b64 {%0, %1}, %2;" : "=f"(lo), "=f"(hi) : "l"(v));
}
__device__ __forceinline__ unsigned long long fma2(unsigned long long a,
                                                   unsigned long long b,
                                                   unsigned long long c) {
    unsigned long long d;
    asm("fma.rn.f32x2 %0, %1, %2, %3;" : "=l"(d) : "l"(a), "l"(b), "l"(c));
    return d;
}

extern __shared__ unsigned long long sm[];

__global__ void __launch_bounds__(THREADS, 2)
potts_k(const float* __restrict__ V,   // [128,1024]
        const float* __restrict__ W,   // [1024,1024]
        float* __restrict__ out)       // [128]
{
    unsigned long long* Wd = sm;              // [HI][WDS] u64 (w,w) dup, masked
    unsigned long long* Xi = sm + HI * WDS;   // [HI i][XS] u64 x-pairs over b
    unsigned long long* Xj = Xi + HI * XS;    // [64 j][XS]
    float* fb   = (float*)(Xj + T * XS);
    float* cs   = fb;                         // [64]
    float* rs   = fb + 64;                    // [32]
    float* wsum = fb + 96;                    // [1] (+pad)
    float* redq = fb + 100;                   // [16][32]
    float* redr = fb + 100 + 512;             // [16][128]
    float* csp  = redq;                       // alias scratch [64][8]
    float* rsp  = redr;                       // alias scratch [32][16]

    const int tid  = threadIdx.x;
    const int warp = tid >> 5;
    const int lane = tid & 31;
    const int bq   = warp & 3;                // b-quarter (32 b)
    const int jq   = warp >> 2;               // j-quarter (16 j)
    const int bgl  = lane >> 2;               // 0..7  -> 4 b each
    const int jgl  = lane & 3;                // 0..3  -> 4 j each
    const int bgidx = bq * 8 + bgl;           // b-pair-pair index (0..31)
    const int jbase = jq * 16 + jgl * 4;      // first of this thread's 4 j

    // ---- CTA -> (tile, i-half) ----
    int k = blockIdx.x >> 1;
    const int h = blockIdx.x & 1;             // i-half: rows [h*32, h*32+32)
    int bi = 0;
    while (k >= NT - bi) { k -= NT - bi; bi++; }
    const int bj   = bi + k;
    const int gi0h = bi * T + h * HI;         // global first i-row of this CTA
    const int gj0  = bj * T;
    const bool diag = (bi == bj);
    const int iofs = h * HI;                  // row offset within tile (for mask)

    // ---- stage W half-tile as duplicated u64, masked (512 float4) ----
    {
        int ii = tid >> 4;                    // 0..31 local row
        int q  = tid & 15;
        float4 w = *(const float4*)(W + (size_t)(gi0h + ii) * Nn + gj0 + q * 4);
        int j0 = q * 4;
        int gr = iofs + ii;                   // row index within tile
        if (diag) {
            if (gr > j0 + 0) w.x = 0.0f;
            if (gr > j0 + 1) w.y = 0.0f;
            if (gr > j0 + 2) w.z = 0.0f;
            if (gr > j0 + 3) w.w = 0.0f;
        }
        ulonglong2* dst = (ulonglong2*)(Wd + ii * WDS + j0);
        dst[0] = make_ulonglong2(pack2(w.x, w.x), pack2(w.y, w.y));
        dst[1] = make_ulonglong2(pack2(w.z, w.z), pack2(w.w, w.w));
    }

    // ---- stage Xi: this half's 32 i-rows, x-pairs over b (1024 float4) ----
    #pragma unroll
    for (int it = 0; it < 2; it++) {
        int idx = it * THREADS + tid;
        int b   = idx >> 3;                   // 0..127
        int q   = idx & 7;                    // 8 float4 = 32 floats
        float4 a = *(const float4*)(V + (size_t)b * Nn + gi0h + q * 4);
        float* xi = (float*)Xi;
        int half = b & 1, bp = b >> 1;
        xi[((q * 4 + 0) * XS + bp) * 2 + half] = a.x;
        xi[((q * 4 + 1) * XS + bp) * 2 + half] = a.y;
        xi[((q * 4 + 2) * XS + bp) * 2 + half] = a.z;
        xi[((q * 4 + 3) * XS + bp) * 2 + half] = a.w;
    }

    // ---- stage Xj: all 64 j, x-pairs over b (2048 float4) ----
    #pragma unroll
    for (int it = 0; it < 4; it++) {
        int idx = it * THREADS + tid;
        int b   = idx >> 4;
        int q   = idx & 15;
        float4 c = *(const float4*)(V + (size_t)b * Nn + gj0 + q * 4);
        float* xj = (float*)Xj;
        int half = b & 1, bp = b >> 1;
        xj[((q * 4 + 0) * XS + bp) * 2 + half] = c.x;
        xj[((q * 4 + 1) * XS + bp) * 2 + half] = c.y;
        xj[((q * 4 + 2) * XS + bp) * 2 + half] = c.z;
        xj[((q * 4 + 3) * XS + bp) * 2 + half] = c.w;
    }
    __syncthreads();

    // ---- cooperative col/row sums of masked half (lo halves of Wd) ----
    {
        const float* Wlo = (const float*)Wd;
        // cs partials: thread (j, c): sum i = 4c..4c+3  (64*8 = 512 threads)
        int j = tid >> 3, c = tid & 7;
        float pc = 0.0f;
        #pragma unroll
        for (int t = 0; t < 4; t++)
            pc += Wlo[((c * 4 + t) * WDS + j) * 2];
        csp[j * 8 + c] = pc;
        __syncthreads();
        // rs partials: thread (i, c): sum j = 4c..4c+3  (32*16 = 512 threads)
        int i = tid >> 4, c2 = tid & 15;
        float pr = 0.0f;
        #pragma unroll
        for (int t = 0; t < 4; t++)
            pr += Wlo[(i * WDS + c2 * 4 + t) * 2];
        // stash cs partial sums before rsp aliasing is read back
        float csv = 0.0f;
        if (tid < 64) {
            #pragma unroll
            for (int c3 = 0; c3 < 8; c3++) csv += csp[tid * 8 + c3];
        }
        __syncthreads();
        rsp[i * 16 + c2] = pr;
        if (tid < 64) cs[tid] = csv;
        __syncthreads();
        if (tid >= 64 && tid < 96) {
            int ir = tid - 64;
            float s = 0.0f;
            #pragma unroll
            for (int c3 = 0; c3 < 16; c3++) s += rsp[ir * 16 + c3];
            rs[ir] = s;
        }
    }
    __syncthreads();
    if (warp == 0) {
        float v = cs[lane] + cs[lane + 32];
        #pragma unroll
        for (int o = 16; o > 0; o >>= 1) v += __shfl_down_sync(0xffffffffu, v, o);
        if (lane == 0) wsum[0] = v;
    }
    __syncthreads();

    // ---- quadratic main loop (32 i): packed s1 over (b0,b1)/(b2,b3) x 4 j ----
    unsigned long long a00 = 0, a01 = 0, a10 = 0, a11 = 0;
    unsigned long long a20 = 0, a21 = 0, a30 = 0, a31 = 0;

    #pragma unroll 8
    for (int i = 0; i < HI; i++) {
        ulonglong2 xp = *(const ulonglong2*)(Xi + i * XS + 2 * bgidx);
        ulonglong2 wA = *(const ulonglong2*)(Wd + i * WDS + jbase);
        ulonglong2 wB = *(const ulonglong2*)(Wd + i * WDS + jbase + 2);
        a00 = fma2(wA.x, xp.x, a00);  a01 = fma2(wA.x, xp.y, a01);
        a10 = fma2(wA.y, xp.x, a10);  a11 = fma2(wA.y, xp.y, a11);
        a20 = fma2(wB.x, xp.x, a20);  a21 = fma2(wB.x, xp.y, a21);
        a30 = fma2(wB.y, xp.x, a30);  a31 = fma2(wB.y, xp.y, a31);
    }

    // ---- epilogue: q(b) += x_bj * (2*s1_bj - cs_j), stays packed ----
    const unsigned long long twodup = pack2(2.0f, 2.0f);
    unsigned long long q0 = 0, q1 = 0;
    {
        unsigned long long accs[4][2] = {{a00,a01},{a10,a11},{a20,a21},{a30,a31}};
        #pragma unroll
        for (int jg = 0; jg < 4; jg++) {
            int j = jbase + jg;
            float csj = cs[j];
            unsigned long long ncs = pack2(-csj, -csj);
            unsigned long long t0 = fma2(accs[jg][0], twodup, ncs);
            unsigned long long t1 = fma2(accs[jg][1], twodup, ncs);
            ulonglong2 vj = *(const ulonglong2*)(Xj + j * XS + 2 * bgidx);
            q0 = fma2(vj.x, t0, q0);
            q1 = fma2(vj.y, t1, q1);
        }
    }
    {
        float f0, f1, f2, f3;
        unpack2(q0, f0, f1);
        unpack2(q1, f2, f3);
        // 4 jgl-lanes share (warp,bgl): jgl in lane bits [1:0] -> xor-reduce
        #pragma unroll
        for (int o = 1; o <= 2; o <<= 1) {
            f0 += __shfl_xor_sync(0xffffffffu, f0, o);
            f1 += __shfl_xor_sync(0xffffffffu, f1, o);
            f2 += __shfl_xor_sync(0xffffffffu, f2, o);
            f3 += __shfl_xor_sync(0xffffffffu, f3, o);
        }
        if (jgl == 0) {
            float* row = redq + warp * 32 + bgl * 4;
            row[0] = f0; row[1] = f1; row[2] = f2; row[3] = f3;
        }
    }

    // ---- linear rs term: warp w covers i = 2w..2w+1, lane covers 4 b ----
    {
        unsigned long long r0 = 0, r1 = 0;
        int i0 = warp * 2;
        #pragma unroll
        for (int t = 0; t < 2; t++) {
            int i = i0 + t;
            unsigned long long rd = pack2(rs[i], rs[i]);
            ulonglong2 xp = *(const ulonglong2*)(Xi + i * XS + 2 * lane);
            r0 = fma2(rd, xp.x, r0);
            r1 = fma2(rd, xp.y, r1);
        }
        float f0, f1, f2, f3;
        unpack2(r0, f0, f1);
        unpack2(r1, f2, f3);
        float* row = redr + warp * 128 + lane * 4;
        row[0] = f0; row[1] = f1; row[2] = f2; row[3] = f3;
    }
    __syncthreads();

    // ---- final per-b reduction + global accumulate ----
    if (tid < Bb) {
        int tbq = tid >> 5, bl = tid & 31;
        float sq = redq[(0 * 4 + tbq) * 32 + bl] + redq[(1 * 4 + tbq) * 32 + bl]
                 + redq[(2 * 4 + tbq) * 32 + bl] + redq[(3 * 4 + tbq) * 32 + bl];
        float sr = 0.0f;
        #pragma unroll
        for (int w = 0; w < 16; w++) sr += redr[w * 128 + tid];
        atomicAdd(&g_accum[tid], sq - sr + wsum[0]);
    }
    __threadfence();
    __syncthreads();

    __shared__ bool last;
    if (tid == 0) last = (atomicAdd(&g_count, 1u) == NCTAS - 1);
    __syncthreads();

    if (last) {
        __threadfence();
        if (tid < Bb) out[tid] = atomicExch(&g_accum[tid], 0.0f);
        if (tid == 0) atomicExch(&g_count, 0u);
    }
}

extern "C" void kernel_launch(void* const* d_in, const int* in_sizes, int n_in,
                              void* d_out, int out_size)
{
    const float* V = (const float*)d_in[0];
    const float* W = (const float*)d_in[1];
    float* out = (float*)d_out;

    const int smem_bytes = (HI * WDS + HI * XS + T * XS) * 8
                         + (100 + 512 + 2048) * 4;   // ~78 KB
    cudaFuncSetAttribute(potts_k, cudaFuncAttributeMaxDynamicSharedMemorySize,
                         smem_bytes);

    potts_k<<<NCTAS, THREADS, smem_bytes>>>(V, W, out);
}

// round 9
// speedup vs baseline: 1.0084x; 1.0084x over previous
#include <cuda_runtime.h>

// Potts energy: out[b] = sum_{i<=j} W[i,j] * [(1-x_i)(1-x_j) + x_i*x_j]
//             = wsum - sum_i rs_i x_i - sum_j cs_j x_j + 2 sum_{i<=j} W_ij x_i x_j
// per 64x64 tile, split into 2 i-halves (32 rows) -> 272 CTAs (~2/SM).
// Mainloop: thread owns (j-group, batch-pair); x packed in registers;
// W read as warp-uniform broadcasts from smem (dup (w,w) u64 rows).

#define Bb      128
#define Nn      1024
#define T       64
#define HI      32
#define NT      16
#define NCTAS   272
#define WDI     34      // Wd row stride (u64), even => 16B-aligned rows
#define XSI     65      // Xi2 row stride (u64)
#define XSJ     65      // Xj2 row stride (u64)
#define THREADS 256

__device__ float        g_accum[Bb];
__device__ unsigned int g_count;

__device__ __forceinline__ unsigned long long pack2(float lo, float hi) {
    unsigned long long r;
    asm("mov.b64 %0, {%1, %2};" : "=l"(r) : "f"(lo), "f"(hi));
    return r;
}
__device__ __forceinline__ void unpack2(unsigned long long v, float& lo, float& hi) {
    asm("mov.b64 {%0, %1}, %2;" : "=f"(lo), "=f"(hi) : "l"(v));
}
__device__ __forceinline__ unsigned long long fma2(unsigned long long a,
                                                   unsigned long long b,
                                                   unsigned long long c) {
    unsigned long long d;
    asm("fma.rn.f32x2 %0, %1, %2, %3;" : "=l"(d) : "l"(a), "l"(b), "l"(c));
    return d;
}
__device__ __forceinline__ unsigned long long add2(unsigned long long a,
                                                   unsigned long long b) {
    unsigned long long d;
    asm("add.rn.f32x2 %0, %1, %2;" : "=l"(d) : "l"(a), "l"(b));
    return d;
}

extern __shared__ unsigned long long sm[];

__global__ void __launch_bounds__(THREADS, 2)
potts_k(const float* __restrict__ V,   // [128,1024]
        const float* __restrict__ W,   // [1024,1024]
        float* __restrict__ out)       // [128]
{
    unsigned long long* Wd   = sm;                 // [64 j][WDI] (w,w) dup, masked
    unsigned long long* Xi2  = Wd + 64 * WDI;      // [32 i][XSI] packed b-pairs
    unsigned long long* Xj2  = Xi2 + HI * XSI;     // [64 j][XSJ]
    unsigned long long* cs2n = Xj2 + T * XSJ;      // [64] (-cs,-cs)
    unsigned long long* rs2n = cs2n + 64;          // [32] (-rs,-rs)
    unsigned long long* red  = rs2n + 32;          // [4][64]
    float* csp  = (float*)(red + 256);             // [64][4]
    float* rsp  = csp + 256;                       // [32][8]
    float* wsum = rsp + 256;                       // [1]

    const int tid  = threadIdx.x;
    const int warp = tid >> 5;
    const int lane = tid & 31;
    const int jg   = warp >> 1;                 // 0..3 -> 16 j each
    const int bpg  = (warp & 1) * 32 + lane;    // 0..63 batch pair

    // ---- CTA -> (tile, i-half) ----
    int k = blockIdx.x >> 1;
    const int h = blockIdx.x & 1;
    int bi = 0;
    while (k >= NT - bi) { k -= NT - bi; bi++; }
    const int bj   = bi + k;
    const int gi0h = bi * T + h * HI;
    const int gj0  = bj * T;
    const bool diag = (bi == bj);
    const int iofs = h * HI;

    // ---- stage W half-tile: transpose -> Wd[j][i] dup, masked (512 float4) ----
    #pragma unroll
    for (int it = 0; it < 2; it++) {
        int idx = it * THREADS + tid;
        int ii  = idx >> 4;                    // 0..31 local i
        int q   = idx & 15;
        float4 w = *(const float4*)(W + (size_t)(gi0h + ii) * Nn + gj0 + q * 4);
        int gr = iofs + ii, j0 = q * 4;
        if (diag) {
            if (gr > j0 + 0) w.x = 0.0f;
            if (gr > j0 + 1) w.y = 0.0f;
            if (gr > j0 + 2) w.z = 0.0f;
            if (gr > j0 + 3) w.w = 0.0f;
        }
        Wd[(j0 + 0) * WDI + ii] = pack2(w.x, w.x);
        Wd[(j0 + 1) * WDI + ii] = pack2(w.y, w.y);
        Wd[(j0 + 2) * WDI + ii] = pack2(w.z, w.z);
        Wd[(j0 + 3) * WDI + ii] = pack2(w.w, w.w);
    }

    // ---- stage Xi2 [32 i][64 bp] (1024 float4) ----
    #pragma unroll
    for (int it = 0; it < 4; it++) {
        int idx = it * THREADS + tid;
        int b   = idx >> 3;                    // 0..127
        int q   = idx & 7;
        float4 a = *(const float4*)(V + (size_t)b * Nn + gi0h + q * 4);
        float* xi = (float*)Xi2;
        int half = b & 1, bp = b >> 1;
        xi[((q * 4 + 0) * XSI + bp) * 2 + half] = a.x;
        xi[((q * 4 + 1) * XSI + bp) * 2 + half] = a.y;
        xi[((q * 4 + 2) * XSI + bp) * 2 + half] = a.z;
        xi[((q * 4 + 3) * XSI + bp) * 2 + half] = a.w;
    }

    // ---- stage Xj2 [64 j][64 bp] (2048 float4) ----
    #pragma unroll
    for (int it = 0; it < 8; it++) {
        int idx = it * THREADS + tid;
        int b   = idx >> 4;
        int q   = idx & 15;
        float4 c = *(const float4*)(V + (size_t)b * Nn + gj0 + q * 4);
        float* xj = (float*)Xj2;
        int half = b & 1, bp = b >> 1;
        xj[((q * 4 + 0) * XSJ + bp) * 2 + half] = c.x;
        xj[((q * 4 + 1) * XSJ + bp) * 2 + half] = c.y;
        xj[((q * 4 + 2) * XSJ + bp) * 2 + half] = c.z;
        xj[((q * 4 + 3) * XSJ + bp) * 2 + half] = c.w;
    }
    __syncthreads();

    // ---- cooperative col/row sums of masked half (lo halves of Wd) ----
    {
        const float* Wlo = (const float*)Wd;
        int jj = tid >> 2, c = tid & 3;        // cs partial: 64 j x 4 chunks of 8 i
        float pc = 0.0f;
        #pragma unroll
        for (int t = 0; t < 8; t++)
            pc += Wlo[(jj * WDI + c * 8 + t) * 2];
        csp[jj * 4 + c] = pc;
        int i2 = tid >> 3, c2 = tid & 7;       // rs partial: 32 i x 8 chunks of 8 j
        float pr = 0.0f;
        #pragma unroll
        for (int t = 0; t < 8; t++)
            pr += Wlo[((c2 * 8 + t) * WDI + i2) * 2];
        rsp[i2 * 8 + c2] = pr;
    }
    __syncthreads();
    if (tid < 64) {
        float s = csp[tid * 4] + csp[tid * 4 + 1] + csp[tid * 4 + 2] + csp[tid * 4 + 3];
        cs2n[tid] = pack2(-s, -s);
    } else if (tid < 96) {
        int i = tid - 64;
        float s = 0.0f;
        #pragma unroll
        for (int c = 0; c < 8; c++) s += rsp[i * 8 + c];
        rs2n[i] = pack2(-s, -s);
    }
    __syncthreads();
    if (warp == 0) {
        const float* cslo = (const float*)cs2n;
        float v = cslo[lane * 2] + cslo[(lane + 32) * 2];
        #pragma unroll
        for (int o = 16; o > 0; o >>= 1) v += __shfl_down_sync(0xffffffffu, v, o);
        if (lane == 0) wsum[0] = -v;           // cs2n holds negated sums
    }

    // ---- preload this thread's packed x over its batch pair ----
    unsigned long long x2[HI];
    #pragma unroll
    for (int i = 0; i < HI; i++) x2[i] = Xi2[i * XSI + bpg];
    __syncthreads();

    // ---- mainloop: 16 j per thread, W rows are warp-uniform broadcasts ----
    const unsigned long long two2 = pack2(2.0f, 2.0f);
    unsigned long long q = 0;
    const int jbase = jg * 16;
    #pragma unroll 4
    for (int jj = 0; jj < 16; jj++) {
        const int j = jbase + jj;
        const ulonglong2* wr = (const ulonglong2*)(Wd + j * WDI);
        unsigned long long a0 = 0, a1 = 0, a2 = 0, a3 = 0;
        #pragma unroll
        for (int kk = 0; kk < 4; kk++) {
            ulonglong2 wA = wr[kk * 4 + 0];
            ulonglong2 wB = wr[kk * 4 + 1];
            ulonglong2 wC = wr[kk * 4 + 2];
            ulonglong2 wD = wr[kk * 4 + 3];
            a0 = fma2(wA.x, x2[kk * 8 + 0], a0);
            a1 = fma2(wA.y, x2[kk * 8 + 1], a1);
            a2 = fma2(wB.x, x2[kk * 8 + 2], a2);
            a3 = fma2(wB.y, x2[kk * 8 + 3], a3);
            a0 = fma2(wC.x, x2[kk * 8 + 4], a0);
            a1 = fma2(wC.y, x2[kk * 8 + 5], a1);
            a2 = fma2(wD.x, x2[kk * 8 + 6], a2);
            a3 = fma2(wD.y, x2[kk * 8 + 7], a3);
        }
        unsigned long long s1 = add2(add2(a0, a1), add2(a2, a3));
        unsigned long long t  = fma2(s1, two2, cs2n[j]);      // broadcast LDS.64
        q = fma2(Xj2[j * XSJ + bpg], t, q);                   // conflict-free LDS.64
    }

    // ---- fold -rs_i * x_bi for this thread's i-chunk (jg*8 .. +8) ----
    #pragma unroll
    for (int t = 0; t < 8; t++) {
        int i = jg * 8 + t;
        q = fma2(rs2n[i], x2[i], q);
    }

    red[jg * 64 + bpg] = q;                    // bijective (jg,bpg) -> no collisions
    __syncthreads();

    // ---- final per-batch-pair reduction + global accumulate ----
    if (tid < 64) {
        unsigned long long s = add2(add2(red[tid], red[64 + tid]),
                                    add2(red[128 + tid], red[192 + tid]));
        float e0, e1;
        unpack2(s, e0, e1);
        float ws = wsum[0];
        atomicAdd(&g_accum[2 * tid + 0], e0 + ws);
        atomicAdd(&g_accum[2 * tid + 1], e1 + ws);
    }
    __threadfence();
    __syncthreads();

    __shared__ bool last;
    if (tid == 0) last = (atomicAdd(&g_count, 1u) == NCTAS - 1);
    __syncthreads();

    if (last) {
        __threadfence();
        if (tid < Bb) out[tid] = atomicExch(&g_accum[tid], 0.0f);
        if (tid == 0) atomicExch(&g_count, 0u);
    }
}

extern "C" void kernel_launch(void* const* d_in, const int* in_sizes, int n_in,
                              void* d_out, int out_size)
{
    const float* V = (const float*)d_in[0];
    const float* W = (const float*)d_in[1];
    float* out = (float*)d_out;

    const int smem_bytes = (64 * WDI + HI * XSI + T * XSJ + 64 + 32 + 256) * 8
                         + (256 + 256 + 4) * 4;   // 72208 B -> 2 CTAs/SM fits
    cudaFuncSetAttribute(potts_k, cudaFuncAttributeMaxDynamicSharedMemorySize,
                         smem_bytes);

    potts_k<<<NCTAS, THREADS, smem_bytes>>>(V, W, out);
}